// round 4
// baseline (speedup 1.0000x reference)
#include <cuda_runtime.h>
#include <cuda_bf16.h>
#include <cstdint>

#define BMAX   64
#define MA     96
#define NDIM   256
#define EPSF   1e-8f
#define SLAB_F4 2304          // 96*96/4 float4 per slab

// Scatter buffer for padded node scores [B, MAX_A].
// Zero-initialized at module load; invalid positions are never written and
// stay 0 (and paths is 0 there anyway), so no explicit zeroing kernel needed.
__device__ float g_sp[BMAX * MA];

// ---------------------------------------------------------------------------
// Kernel 1: scores = x @ W[0] + b[0], scattered into g_sp via pad_idx.
// One warp per node: 256 dims = 2 float4 per lane, shfl reduce.
// ---------------------------------------------------------------------------
__global__ void score_scatter_kernel(const float* __restrict__ x,
                                     const float* __restrict__ W,
                                     const float* __restrict__ bscal,
                                     const int*   __restrict__ pad_idx,
                                     int total) {
    int gwarp = (blockIdx.x * blockDim.x + threadIdx.x) >> 5;
    int lane  = threadIdx.x & 31;
    if (gwarp >= total) return;

    const float4* xr = reinterpret_cast<const float4*>(x + (size_t)gwarp * NDIM);
    const float4* wr = reinterpret_cast<const float4*>(W);

    float s = 0.0f;
    #pragma unroll
    for (int i = 0; i < 2; i++) {
        float4 a  = xr[lane + i * 32];
        float4 ww = wr[lane + i * 32];
        s += a.x * ww.x + a.y * ww.y + a.z * ww.z + a.w * ww.w;
    }
    #pragma unroll
    for (int o = 16; o > 0; o >>= 1)
        s += __shfl_xor_sync(0xFFFFFFFFu, s, o);

    if (lane == 0)
        g_sp[pad_idx[gwarp]] = s + bscal[0];
}

// ---------------------------------------------------------------------------
// Kernel 2 (the 226 MB pass): barrier-free streaming, one warp per row.
// Block = 8 warps over one (b,i) slab; warp w owns 12 consecutive rows.
// Lanes 0-23 each hold one float4 of the row (384B contiguous, fully
// coalesced). sp4[lane] is register-resident (constant per graph).
// 6 rows' loads issued back-to-back for MLP, then butterfly-reduced.
// No shared memory, no __syncthreads.
// ---------------------------------------------------------------------------
__global__ __launch_bounds__(256, 4) void path_avg_kernel(
        const float4* __restrict__ paths4,
        float*        __restrict__ out) {
    int bi   = blockIdx.x;            // b * MA + i
    int b    = bi / MA;
    int t    = threadIdx.x;
    int w    = t >> 5;
    int lane = t & 31;

    float4 s = make_float4(0.f, 0.f, 0.f, 0.f);
    if (lane < 24)
        s = reinterpret_cast<const float4*>(g_sp + b * MA)[lane];

    const float4* base = paths4 + (size_t)bi * SLAB_F4 + w * 12 * 24;
    float*        orow = out    + (size_t)bi * MA      + w * 12;

    #pragma unroll
    for (int gg = 0; gg < 2; gg++) {
        float4 v[6];
        #pragma unroll
        for (int r = 0; r < 6; r++) {
            v[r] = make_float4(0.f, 0.f, 0.f, 0.f);
            if (lane < 24)
                v[r] = base[(gg * 6 + r) * 24 + lane];
        }
        #pragma unroll
        for (int r = 0; r < 6; r++) {
            float num = v[r].x * s.x + v[r].y * s.y + v[r].z * s.z + v[r].w * s.w;
            float den = (v[r].x + v[r].y) + (v[r].z + v[r].w);
            #pragma unroll
            for (int o = 16; o > 0; o >>= 1) {
                num += __shfl_xor_sync(0xFFFFFFFFu, num, o);
                den += __shfl_xor_sync(0xFFFFFFFFu, den, o);
            }
            if (lane == 0)
                orow[gg * 6 + r] = num / (den + EPSF);
        }
    }
}

// ---------------------------------------------------------------------------
// Launch. Inputs (metadata order): x, W, b, paths, pad_idx.
// ---------------------------------------------------------------------------
extern "C" void kernel_launch(void* const* d_in, const int* in_sizes, int n_in,
                              void* d_out, int out_size) {
    const float*  x       = (const float*)d_in[0];
    const float*  W       = (const float*)d_in[1];
    const float*  bscal   = (const float*)d_in[2];
    const float4* paths4  = (const float4*)d_in[3];
    const int*    pad_idx = (const int*)d_in[4];
    float*        out     = (float*)d_out;

    int total = in_sizes[4];   // number of valid nodes

    // 1: scores + scatter (one warp per node)
    int blocks1 = (total * 32 + 255) / 256;
    score_scatter_kernel<<<blocks1, 256>>>(x, W, bscal, pad_idx, total);

    // 2: main fused pass over paths (barrier-free streaming)
    path_avg_kernel<<<BMAX * MA, 256>>>(paths4, out);
}

// round 5
// speedup vs baseline: 1.3371x; 1.3371x over previous
#include <cuda_runtime.h>
#include <cuda_bf16.h>
#include <cstdint>

#define BMAX    64
#define MA      96
#define NDIM    256
#define EPSF    1e-8f
#define SLAB_F4 2304                 // 96*96/4 float4 per slab
#define NSLABS  (BMAX * MA)          // 6144
#define GRID2   296                  // 2 blocks per SM * 148 SMs

// Scatter buffer for padded node scores [B, MAX_A]. Zero-init at module load;
// invalid positions never written (and paths is 0 there anyway).
__device__ float g_sp[BMAX * MA];

__device__ __forceinline__ void cp16(float4* dst_smem, const float4* src_gmem) {
    uint32_t d = (uint32_t)__cvta_generic_to_shared(dst_smem);
    asm volatile("cp.async.cg.shared.global [%0], [%1], 16;\n"
                 :: "r"(d), "l"(src_gmem) : "memory");
}
__device__ __forceinline__ void cp_commit() {
    asm volatile("cp.async.commit_group;\n" ::: "memory");
}
__device__ __forceinline__ void cp_wait1() {
    asm volatile("cp.async.wait_group 1;\n" ::: "memory");
}

// ---------------------------------------------------------------------------
// Kernel 1: scores = x @ W[0] + b[0], scattered into g_sp via pad_idx.
// ---------------------------------------------------------------------------
__global__ void score_scatter_kernel(const float* __restrict__ x,
                                     const float* __restrict__ W,
                                     const float* __restrict__ bscal,
                                     const int*   __restrict__ pad_idx,
                                     int total) {
    int gwarp = (blockIdx.x * blockDim.x + threadIdx.x) >> 5;
    int lane  = threadIdx.x & 31;
    if (gwarp >= total) return;

    const float4* xr = reinterpret_cast<const float4*>(x + (size_t)gwarp * NDIM);
    const float4* wr = reinterpret_cast<const float4*>(W);

    float s = 0.0f;
    #pragma unroll
    for (int i = 0; i < 2; i++) {
        float4 a  = xr[lane + i * 32];
        float4 ww = wr[lane + i * 32];
        s += a.x * ww.x + a.y * ww.y + a.z * ww.z + a.w * ww.w;
    }
    #pragma unroll
    for (int o = 16; o > 0; o >>= 1)
        s += __shfl_xor_sync(0xFFFFFFFFu, s, o);

    if (lane == 0)
        g_sp[pad_idx[gwarp]] = s + bscal[0];
}

// ---------------------------------------------------------------------------
// Kernel 2: persistent double-buffered cp.async pipeline over slabs.
// Each block grid-strides over slabs; prefetches slab k+1 into the other
// buffer while computing slab k. Compute: 192 threads = 2 per row (12 f4
// each, XOR-swizzled conflict-free LDS.128), one shfl-pair to combine.
// ---------------------------------------------------------------------------
extern __shared__ float4 s_dyn[];   // [2][SLAB_F4] slabs, then [24] sp

__global__ __launch_bounds__(256) void path_avg_kernel(
        const float4* __restrict__ paths4,
        float*        __restrict__ out) {
    float4* buf0 = s_dyn;
    float4* buf1 = s_dyn + SLAB_F4;
    float4* sp_s = s_dyn + 2 * SLAB_F4;   // 24 float4 = 96 floats
    const float4* g_sp4 = reinterpret_cast<const float4*>(g_sp);

    int t  = threadIdx.x;
    int nb = gridDim.x;
    int s0 = blockIdx.x;

    // Stage slab -> buffer with XOR swizzle, 9 cp.async per thread.
    auto stage = [&](int slab, float4* dst) {
        const float4* src = paths4 + (size_t)slab * SLAB_F4;
        #pragma unroll
        for (int i = 0; i < 9; i++) {
            int f = t + i * 256;
            int r = f / 24;
            int c = f - r * 24;
            cp16(dst + r * 24 + (c ^ (r & 7)), src + f);
        }
    };

    if (s0 < NSLABS) stage(s0, buf0);
    cp_commit();

    int k = 0;
    for (int s = s0; s < NSLABS; s += nb, k++) {
        // sp for this slab's graph (prev compute finished at last barrier)
        if (t < 24) sp_s[t] = g_sp4[(s / MA) * 24 + t];

        int snext = s + nb;
        float4* cur = (k & 1) ? buf1 : buf0;
        float4* nxt = (k & 1) ? buf0 : buf1;
        if (snext < NSLABS) stage(snext, nxt);
        cp_commit();

        cp_wait1();              // slab s resident (snext may be in flight)
        __syncthreads();

        if (t < 192) {
            int r  = t >> 1;
            int h  = t & 1;
            int sw = r & 7;
            const float4* row = cur + r * 24;
            float num = 0.0f, den = 0.0f;
            #pragma unroll
            for (int j = 0; j < 12; j++) {
                int c = h * 12 + j;
                float4 p = row[c ^ sw];
                float4 sv = sp_s[c];
                num += p.x * sv.x + p.y * sv.y + p.z * sv.z + p.w * sv.w;
                den += (p.x + p.y) + (p.z + p.w);
            }
            num += __shfl_xor_sync(0xFFFFFFFFu, num, 1);
            den += __shfl_xor_sync(0xFFFFFFFFu, den, 1);
            if (h == 0)
                out[(size_t)s * MA + r] = num / (den + EPSF);
        }
        __syncthreads();         // protect cur buffer + sp_s before reuse
    }
}

// ---------------------------------------------------------------------------
// Launch. Inputs (metadata order): x, W, b, paths, pad_idx.
// ---------------------------------------------------------------------------
extern "C" void kernel_launch(void* const* d_in, const int* in_sizes, int n_in,
                              void* d_out, int out_size) {
    const float*  x       = (const float*)d_in[0];
    const float*  W       = (const float*)d_in[1];
    const float*  bscal   = (const float*)d_in[2];
    const float4* paths4  = (const float4*)d_in[3];
    const int*    pad_idx = (const int*)d_in[4];
    float*        out     = (float*)d_out;

    int total = in_sizes[4];

    // 1: scores + scatter
    int blocks1 = (total * 32 + 255) / 256;
    score_scatter_kernel<<<blocks1, 256>>>(x, W, bscal, pad_idx, total);

    // 2: persistent double-buffered pass over paths
    size_t smem = (2 * SLAB_F4 + 24) * sizeof(float4);   // 74112 B
    cudaFuncSetAttribute(path_avg_kernel,
                         cudaFuncAttributeMaxDynamicSharedMemorySize,
                         (int)smem);
    path_avg_kernel<<<GRID2, 256, smem>>>(paths4, out);
}